// round 11
// baseline (speedup 1.0000x reference)
#include <cuda_runtime.h>
#include <cuda_fp16.h>
#include <cstdint>

static constexpr int KDIM = 4096;
static constexpr int NDIM = 4096;
static constexpr int BDIM = 8192;
static constexpr int BK   = 64;
static constexpr int NCH  = KDIM / BK;                 // 64 chunks
static constexpr int STAGE_A = 0;
static constexpr int STAGE_W = 16384;
static constexpr int STAGE_BYTES = 32768;
static constexpr int NSTAGE = 3;
static constexpr int OFF_BS  = NSTAGE * STAGE_BYTES;   // 98304
static constexpr int OFF_GW  = OFF_BS + 512;
static constexpr int OFF_GB  = OFF_GW + 512;
static constexpr int OFF_RED = OFF_GB + 512;
static constexpr int SMEM_BYTES = OFF_RED + 4096;      // 103936 -> 2 CTAs/SM

__device__ __align__(16) __half g_xh[(size_t)BDIM * KDIM];   // 64 MB
__device__ __align__(16) __half g_wh[(size_t)NDIM * KDIM];   // 32 MB

#define DINL __device__ __forceinline__

DINL uint32_t smem_u32(const void* p) {
    uint32_t a;
    asm("{ .reg .u64 t; cvta.to.shared.u64 t, %1; cvt.u32.u64 %0, t; }" : "=r"(a) : "l"(p));
    return a;
}
DINL void cp_commit() { asm volatile("cp.async.commit_group;" ::: "memory"); }
template <int N> DINL void cp_wait() { asm volatile("cp.async.wait_group %0;" :: "n"(N) : "memory"); }

// cp.async with immediate dst offset (stage baked in at compile time)
#define CPA16_I(dst, IMM, src)                                                      \
    asm volatile("cp.async.cg.shared.global [%0+" IMM "], [%1], 16;"                \
        :: "r"(dst), "l"(src) : "memory")

// ldmatrix x4 with immediate address offset
#define LDMX4_I(d, addr, IMM)                                                       \
    asm volatile("ldmatrix.sync.aligned.m8n8.x4.shared.b16 {%0,%1,%2,%3}, [%4+" IMM "];" \
        : "=r"((d)[0]), "=r"((d)[1]), "=r"((d)[2]), "=r"((d)[3]) : "r"(addr))

#define MMA16816(c, a, b0, b1)                                                      \
    asm volatile("mma.sync.aligned.m16n8k16.row.col.f32.f16.f16.f32 "               \
        "{%0,%1,%2,%3}, {%4,%5,%6,%7}, {%8,%9}, {%0,%1,%2,%3};"                     \
        : "+f"((c)[0]), "+f"((c)[1]), "+f"((c)[2]), "+f"((c)[3])                    \
        : "r"((a)[0]), "r"((a)[1]), "r"((a)[2]), "r"((a)[3]), "r"(b0), "r"(b1))

// consume one chunk resident at stage immediate S0 (A second half at S0+2048)
#define DO_MMA(S0, S1)                                                              \
    do {                                                                            \
        _Pragma("unroll")                                                           \
        for (int kt = 0; kt < 4; ++kt) {                                            \
            uint32_t csw = (uint32_t)((kt * 2 + lhalf) ^ lxor) * 16;                \
            uint32_t aa = a_row + csw, wa = w_row + csw;                            \
            uint32_t af[2][4], bf[2][4];                                            \
            LDMX4_I(af[0], aa, S0);                                                 \
            LDMX4_I(af[1], aa, S1);                                                 \
            LDMX4_I(bf[0], wa, S0);                                                 \
            LDMX4_I(bf[1], wa, S1);                                                 \
            _Pragma("unroll")                                                       \
            for (int mt = 0; mt < 2; ++mt)                                          \
                _Pragma("unroll")                                                   \
                for (int nt = 0; nt < 4; ++nt)                                      \
                    MMA16816(acc[mt][nt], af[mt], bf[nt >> 1][nt & 1],              \
                             bf[nt >> 1][(nt & 1) + 2]);                            \
        }                                                                           \
    } while (0)

// stage chunk at (ga,gw)+SOFF*64 halves into stage immediate SIMM
#define ISSUE(SOFF, SIMM)                                                           \
    do {                                                                            \
        CPA16_I(sts_a0, SIMM, ga + (SOFF) * 64);                                    \
        CPA16_I(sts_a1, SIMM, ga + (SOFF) * 64 + 8);                                \
        CPA16_I(sts_w0, SIMM, gw + (SOFF) * 64);                                    \
        CPA16_I(sts_w1, SIMM, gw + (SOFF) * 64 + 8);                                \
        cp_commit();                                                                \
    } while (0)

// ---------------- fp32 -> fp16 pre-convert (both tensors, one launch) ----------------
static constexpr int XBLK = (int)((size_t)BDIM * KDIM / 2048);   // 16384
static constexpr int WBLK = (int)((size_t)NDIM * KDIM / 2048);   // 8192

__global__ void __launch_bounds__(256) cvt2_kernel(const float* __restrict__ x,
                                                   const float* __restrict__ w,
                                                   __half* __restrict__ xh,
                                                   __half* __restrict__ wh) {
    int b = blockIdx.x;
    const float* src; __half* dst;
    size_t base;
    if (b < XBLK) { src = x; dst = xh; base = (size_t)b * 2048; }
    else          { src = w; dst = wh; base = (size_t)(b - XBLK) * 2048; }
    size_t i = base + (size_t)threadIdx.x * 8;
    float4 f0 = *(const float4*)(src + i);
    float4 f1 = *(const float4*)(src + i + 4);
    __half2 h0 = __floats2half2_rn(f0.x, f0.y);
    __half2 h1 = __floats2half2_rn(f0.z, f0.w);
    __half2 h2 = __floats2half2_rn(f1.x, f1.y);
    __half2 h3 = __floats2half2_rn(f1.z, f1.w);
    uint4 v = {*(uint32_t*)&h0, *(uint32_t*)&h1, *(uint32_t*)&h2, *(uint32_t*)&h3};
    *(uint4*)(dst + i) = v;
}

// ---------------- fused GEMM + bias + hardtanh + mish + GroupNorm ----------------
__global__ void __launch_bounds__(512, 2)
fused_gemm_mish_gn(const float* __restrict__ bl, const float* __restrict__ be,
                   const float* __restrict__ gwp, const float* __restrict__ gbp,
                   float* __restrict__ out) {
    extern __shared__ __align__(16) unsigned char sm[];
    const uint32_t sb = smem_u32(sm);

    const int tid  = threadIdx.x;
    const int lane = tid & 31;
    const int wid  = tid >> 5;         // 16 warps
    const int wn   = wid & 3;          // 4 col-blocks of 32
    const int wm   = wid >> 2;         // 4 row-blocks of 32
    const int m0   = blockIdx.y << 7;
    const int n0   = blockIdx.x << 7;

    float* bs  = (float*)(sm + OFF_BS);
    float* gws = (float*)(sm + OFF_GW);
    float* gbs = (float*)(sm + OFF_GB);
    float2* red = (float2*)(sm + OFF_RED);

    if (tid < 128) {
        bs[tid]  = bl[n0 + tid] + be[n0 + tid];
        gws[tid] = gwp[n0 + tid];
        gbs[tid] = gbp[n0 + tid];
    }

    // ---- producer setup: thread t -> row (t>>2), two 16B chunks (t&3)*2+{0,1} ----
    const int ld_row = tid >> 2;
    const int ld_cb  = (tid & 3) * 2;
    const uint32_t sts_a0 = sb + STAGE_A + (uint32_t)ld_row * 128 + (uint32_t)(ld_cb ^ (ld_row & 7)) * 16;
    const uint32_t sts_a1 = sb + STAGE_A + (uint32_t)ld_row * 128 + (uint32_t)((ld_cb + 1) ^ (ld_row & 7)) * 16;
    const uint32_t sts_w0 = sts_a0 + STAGE_W;
    const uint32_t sts_w1 = sts_a1 + STAGE_W;
    const __half* ga = g_xh + (size_t)(m0 + ld_row) * KDIM + ld_cb * 8;
    const __half* gw = g_wh + (size_t)(n0 + ld_row) * KDIM + ld_cb * 8;

    // ---- consumer setup ----
    float acc[2][4][4];
#pragma unroll
    for (int i = 0; i < 2; ++i)
#pragma unroll
        for (int j = 0; j < 4; ++j)
#pragma unroll
            for (int k = 0; k < 4; ++k) acc[i][j][k] = 0.f;

    const uint32_t a_row = sb + STAGE_A + (uint32_t)(wm * 32 + (lane & 15)) * 128;
    const uint32_t w_row = sb + STAGE_W + (uint32_t)(wn * 32 + (lane & 15)) * 128;
    const int lhalf = lane >> 4;
    const int lxor  = lane & 7;

    // ---- prologue: chunks 0 (stage 0) and 1 (stage 1) ----
    ISSUE(0, "0");
    ISSUE(1, "32768");
    ga += 2 * BK; gw += 2 * BK;        // now at chunk 2
    cp_wait<1>();
    __syncthreads();

    // ---- mainloop: 20 iterations x 3 chunks; all stage offsets are immediates ----
#pragma unroll 1
    for (int i = 0; i < 20; ++i) {
        ISSUE(0, "65536");             // chunk 3i+2 -> stage 2
        DO_MMA("0", "2048");           // chunk 3i   @ stage 0
        cp_wait<1>(); __syncthreads();

        ISSUE(1, "0");                 // chunk 3i+3 -> stage 0
        DO_MMA("32768", "34816");      // chunk 3i+1 @ stage 1
        cp_wait<1>(); __syncthreads();

        ISSUE(2, "32768");             // chunk 3i+4 -> stage 1
        DO_MMA("65536", "67584");      // chunk 3i+2 @ stage 2
        cp_wait<1>(); __syncthreads();

        ga += 3 * BK; gw += 3 * BK;
    }

    // ---- tail: chunks 60..63 (60 ready, 61 in flight; ga at chunk 62) ----
    ISSUE(0, "65536");                 // chunk 62 -> stage 2
    DO_MMA("0", "2048");               // chunk 60 @ stage 0
    cp_wait<1>(); __syncthreads();

    ISSUE(1, "0");                     // chunk 63 -> stage 0
    DO_MMA("32768", "34816");          // chunk 61 @ stage 1
    cp_wait<1>(); __syncthreads();

    DO_MMA("65536", "67584");          // chunk 62 @ stage 2
    cp_wait<0>(); __syncthreads();

    DO_MMA("0", "2048");               // chunk 63 @ stage 0

    // ---- fused epilogue: bias -> hardtanh -> mish -> GroupNorm (group == 128 ch) ----
    float ps[2][2], pq[2][2];
#pragma unroll
    for (int mt = 0; mt < 2; ++mt)
#pragma unroll
        for (int rr = 0; rr < 2; ++rr) { ps[mt][rr] = 0.f; pq[mt][rr] = 0.f; }

#pragma unroll
    for (int mt = 0; mt < 2; ++mt)
#pragma unroll
        for (int nt = 0; nt < 4; ++nt)
#pragma unroll
            for (int rr = 0; rr < 2; ++rr)
#pragma unroll
                for (int j = 0; j < 2; ++j) {
                    int n = wn * 32 + nt * 8 + (lane & 3) * 2 + j;
                    float y = acc[mt][nt][rr * 2 + j] + bs[n];
                    y = fminf(1.0f, fmaxf(-1.0f, y));        // hardtanh
                    float z = 1.0f + __expf(y);              // mish: y*(z^2-1)/(z^2+1)
                    float z2 = z * z;
                    float m = y * __fdividef(z2 - 1.0f, z2 + 1.0f);
                    acc[mt][nt][rr * 2 + j] = m;
                    ps[mt][rr] += m;
                    pq[mt][rr] = fmaf(m, m, pq[mt][rr]);
                }

#pragma unroll
    for (int mt = 0; mt < 2; ++mt)
#pragma unroll
        for (int rr = 0; rr < 2; ++rr) {
            float s = ps[mt][rr], q = pq[mt][rr];
            s += __shfl_xor_sync(0xFFFFFFFFu, s, 1);
            q += __shfl_xor_sync(0xFFFFFFFFu, q, 1);
            s += __shfl_xor_sync(0xFFFFFFFFu, s, 2);
            q += __shfl_xor_sync(0xFFFFFFFFu, q, 2);
            if ((lane & 3) == 0) {
                int row = wm * 32 + mt * 16 + (lane >> 2) + rr * 8;
                red[row * 4 + wn] = make_float2(s, q);
            }
        }
    __syncthreads();

#pragma unroll
    for (int mt = 0; mt < 2; ++mt)
#pragma unroll
        for (int rr = 0; rr < 2; ++rr) {
            int row = wm * 32 + mt * 16 + (lane >> 2) + rr * 8;
            float2 r0 = red[row * 4 + 0], r1 = red[row * 4 + 1];
            float2 r2 = red[row * 4 + 2], r3 = red[row * 4 + 3];
            float s = r0.x + r1.x + r2.x + r3.x;
            float q = r0.y + r1.y + r2.y + r3.y;
            float mean = s * 0.0078125f;
            float var  = fmaf(-mean, mean, q * 0.0078125f);
            float rs   = rsqrtf(var + 1e-5f);
            float* orow = out + (size_t)(m0 + row) * NDIM + n0;
#pragma unroll
            for (int nt = 0; nt < 4; ++nt) {
                int n = wn * 32 + nt * 8 + (lane & 3) * 2;
                float2 o;
                o.x = fmaf((acc[mt][nt][rr * 2 + 0] - mean) * rs, gws[n + 0], gbs[n + 0]);
                o.y = fmaf((acc[mt][nt][rr * 2 + 1] - mean) * rs, gws[n + 1], gbs[n + 1]);
                *(float2*)(orow + n) = o;
            }
        }
}

// ---------------- launch ----------------
extern "C" void kernel_launch(void* const* d_in, const int* in_sizes, int n_in,
                              void* d_out, int out_size) {
    const float* x  = (const float*)d_in[0];
    const float* w  = (const float*)d_in[1];
    const float* bl = (const float*)d_in[2];
    const float* be = (const float*)d_in[3];
    const float* gw = (const float*)d_in[4];
    const float* gb = (const float*)d_in[5];
    float* out = (float*)d_out;

    static __half* xh_p = nullptr;
    static __half* wh_p = nullptr;
    if (!xh_p) {
        cudaGetSymbolAddress((void**)&xh_p, g_xh);
        cudaGetSymbolAddress((void**)&wh_p, g_wh);
        cudaFuncSetAttribute(fused_gemm_mish_gn,
                             cudaFuncAttributeMaxDynamicSharedMemorySize, SMEM_BYTES);
    }

    cvt2_kernel<<<XBLK + WBLK, 256>>>(x, w, xh_p, wh_p);

    dim3 grid(NDIM / 128, BDIM / 128);   // (32, 64)
    fused_gemm_mish_gn<<<grid, 512, SMEM_BYTES>>>(bl, be, gw, gb, out);
}